// round 1
// baseline (speedup 1.0000x reference)
#include <cuda_runtime.h>
#include <math.h>
#include <stdint.h>

// Problem dims (fixed by the reference)
#define BATCH 4096
#define DIN   4096
#define HID   2048
#define DOUT  1000
#define LN_EPS 1e-5f

// GEMM tiling
#define BM 128
#define BN 128
#define BK 16
#define TM 8
#define TN 8
#define NTHREADS 256   // (BM/TM)*(BN/TN)

// Scratch (allocation-free rule: __device__ globals)
__device__ float g_h1[(size_t)BATCH * HID];   // h1, later reused as z (normalized h2)
__device__ float g_h2[(size_t)BATCH * HID];
__device__ float g_Wf[(size_t)DOUT * HID];    // folded fc weight
__device__ float g_bf[DOUT];                  // folded fc bias

// ---------------------------------------------------------------------------
// C[M,N] = epi( A[M,K] * B[N,K]^T + bias1[n] (+ bias2[n]) ), row-major A/B/C.
// GUARD_N handles N not divisible by BN (GEMM3, N=1000). M,K must divide tiles.
// ---------------------------------------------------------------------------
template<bool TANH, bool GUARD_N>
__global__ __launch_bounds__(NTHREADS)
void gemm_nt_kernel(const float* __restrict__ A,
                    const float* __restrict__ B,
                    const float* __restrict__ bias1,
                    const float* __restrict__ bias2,
                    float* __restrict__ C,
                    int M, int N, int K)
{
    __shared__ float As[BK][BM + 4];   // +4 keeps 16B alignment & kills bank conflicts
    __shared__ float Bs[BK][BN + 4];

    const int tid = threadIdx.x;
    const int tx = tid & 15;          // n-dir thread
    const int ty = tid >> 4;          // m-dir thread
    const int m0 = blockIdx.y * BM;
    const int n0 = blockIdx.x * BN;

    float acc[TM][TN];
    #pragma unroll
    for (int i = 0; i < TM; i++)
        #pragma unroll
        for (int j = 0; j < TN; j++) acc[i][j] = 0.f;

    for (int kt = 0; kt < K; kt += BK) {
        // ---- load A tile: 128 rows x 16 k = 512 float4, 2 per thread ----
        #pragma unroll
        for (int l = 0; l < 2; l++) {
            int idx = tid + l * NTHREADS;
            int row = idx >> 2;
            int c4  = (idx & 3) * 4;
            float4 v = *reinterpret_cast<const float4*>(
                A + (size_t)(m0 + row) * K + kt + c4);
            As[c4 + 0][row] = v.x;
            As[c4 + 1][row] = v.y;
            As[c4 + 2][row] = v.z;
            As[c4 + 3][row] = v.w;
        }
        // ---- load B tile ----
        #pragma unroll
        for (int l = 0; l < 2; l++) {
            int idx = tid + l * NTHREADS;
            int row = idx >> 2;
            int c4  = (idx & 3) * 4;
            float4 v = make_float4(0.f, 0.f, 0.f, 0.f);
            if (!GUARD_N || (n0 + row) < N)
                v = *reinterpret_cast<const float4*>(
                    B + (size_t)(n0 + row) * K + kt + c4);
            Bs[c4 + 0][row] = v.x;
            Bs[c4 + 1][row] = v.y;
            Bs[c4 + 2][row] = v.z;
            Bs[c4 + 3][row] = v.w;
        }
        __syncthreads();

        #pragma unroll
        for (int k = 0; k < BK; k++) {
            float a[TM], b[TN];
            float4 a0 = *reinterpret_cast<const float4*>(&As[k][ty * TM]);
            float4 a1 = *reinterpret_cast<const float4*>(&As[k][ty * TM + 4]);
            float4 b0 = *reinterpret_cast<const float4*>(&Bs[k][tx * TN]);
            float4 b1 = *reinterpret_cast<const float4*>(&Bs[k][tx * TN + 4]);
            a[0]=a0.x; a[1]=a0.y; a[2]=a0.z; a[3]=a0.w;
            a[4]=a1.x; a[5]=a1.y; a[6]=a1.z; a[7]=a1.w;
            b[0]=b0.x; b[1]=b0.y; b[2]=b0.z; b[3]=b0.w;
            b[4]=b1.x; b[5]=b1.y; b[6]=b1.z; b[7]=b1.w;
            #pragma unroll
            for (int i = 0; i < TM; i++)
                #pragma unroll
                for (int j = 0; j < TN; j++)
                    acc[i][j] = fmaf(a[i], b[j], acc[i][j]);
        }
        __syncthreads();
    }

    // ---- epilogue ----
    #pragma unroll
    for (int i = 0; i < TM; i++) {
        int m = m0 + ty * TM + i;
        #pragma unroll
        for (int j = 0; j < TN; j++) {
            int n = n0 + tx * TN + j;
            if (GUARD_N && n >= N) continue;
            float v = acc[i][j] + bias1[n];
            if (bias2) v += bias2[n];
            if (TANH) v = tanhf(v);
            C[(size_t)m * N + n] = v;
        }
    }
}

// ---------------------------------------------------------------------------
// Per-row LayerNorm of concat([h2,h2]) collapses to mean/var over H.
// Writes z = (h2 - mu) * rsqrt(var + eps). ln_g/ln_b already folded into Wf/bf.
// One block (256 threads) per row; 2048 floats = 512 float4.
// ---------------------------------------------------------------------------
__global__ __launch_bounds__(256)
void rowln_kernel(const float* __restrict__ h2, float* __restrict__ z)
{
    const int row = blockIdx.x;
    const float4* p = reinterpret_cast<const float4*>(h2 + (size_t)row * HID);
    float4 v0 = p[threadIdx.x];
    float4 v1 = p[threadIdx.x + 256];

    float s  = v0.x + v0.y + v0.z + v0.w + v1.x + v1.y + v1.z + v1.w;
    float s2 = v0.x*v0.x + v0.y*v0.y + v0.z*v0.z + v0.w*v0.w
             + v1.x*v1.x + v1.y*v1.y + v1.z*v1.z + v1.w*v1.w;

    #pragma unroll
    for (int o = 16; o > 0; o >>= 1) {
        s  += __shfl_xor_sync(0xffffffffu, s,  o);
        s2 += __shfl_xor_sync(0xffffffffu, s2, o);
    }
    __shared__ float ss[8], ss2[8];
    int w = threadIdx.x >> 5;
    if ((threadIdx.x & 31) == 0) { ss[w] = s; ss2[w] = s2; }
    __syncthreads();
    if (threadIdx.x < 32) {
        float a  = (threadIdx.x < 8) ? ss[threadIdx.x]  : 0.f;
        float a2 = (threadIdx.x < 8) ? ss2[threadIdx.x] : 0.f;
        #pragma unroll
        for (int o = 4; o > 0; o >>= 1) {
            a  += __shfl_xor_sync(0xffffffffu, a,  o);
            a2 += __shfl_xor_sync(0xffffffffu, a2, o);
        }
        if (threadIdx.x == 0) { ss[0] = a; ss2[0] = a2; }
    }
    __syncthreads();

    const float inv = 1.f / (float)HID;
    float mu  = ss[0] * inv;
    float var = ss2[0] * inv - mu * mu;
    float rs  = rsqrtf(var + LN_EPS);

    v0.x = (v0.x - mu) * rs; v0.y = (v0.y - mu) * rs;
    v0.z = (v0.z - mu) * rs; v0.w = (v0.w - mu) * rs;
    v1.x = (v1.x - mu) * rs; v1.y = (v1.y - mu) * rs;
    v1.z = (v1.z - mu) * rs; v1.w = (v1.w - mu) * rs;

    float4* zp = reinterpret_cast<float4*>(z + (size_t)row * HID);
    zp[threadIdx.x]       = v0;
    zp[threadIdx.x + 256] = v1;
}

// Wf[o,j] = ln_g[j]*fcW[o,j] + ln_g[H+j]*fcW[o,H+j]
__global__ __launch_bounds__(256)
void prep_w_kernel(const float* __restrict__ fcW, const float* __restrict__ ln_g,
                   float* __restrict__ Wf)
{
    int idx = blockIdx.x * 256 + threadIdx.x;
    if (idx >= DOUT * HID) return;
    int o = idx / HID;
    int j = idx - o * HID;
    const float* wr = fcW + (size_t)o * (2 * HID);
    Wf[idx] = ln_g[j] * wr[j] + ln_g[HID + j] * wr[HID + j];
}

// bf[o] = fc_b[o] + sum_{j<2H} ln_b[j]*fcW[o,j]
__global__ __launch_bounds__(256)
void prep_b_kernel(const float* __restrict__ fcW, const float* __restrict__ ln_b,
                   const float* __restrict__ fcb, float* __restrict__ bf)
{
    int o = blockIdx.x;
    const float* wr = fcW + (size_t)o * (2 * HID);
    float s = 0.f;
    for (int j = threadIdx.x; j < 2 * HID; j += 256)
        s = fmaf(ln_b[j], wr[j], s);
    #pragma unroll
    for (int ofs = 16; ofs > 0; ofs >>= 1)
        s += __shfl_xor_sync(0xffffffffu, s, ofs);
    __shared__ float ss[8];
    int w = threadIdx.x >> 5;
    if ((threadIdx.x & 31) == 0) ss[w] = s;
    __syncthreads();
    if (threadIdx.x == 0) {
        float a = 0.f;
        #pragma unroll
        for (int i = 0; i < 8; i++) a += ss[i];
        bf[o] = fcb[o] + a;
    }
}

extern "C" void kernel_launch(void* const* d_in, const int* in_sizes, int n_in,
                              void* d_out, int out_size)
{
    const float* x     = (const float*)d_in[0];
    const float* W0    = (const float*)d_in[1];
    const float* b_ih0 = (const float*)d_in[2];
    const float* b_hh0 = (const float*)d_in[3];
    const float* W1    = (const float*)d_in[4];
    const float* b_ih1 = (const float*)d_in[5];
    const float* b_hh1 = (const float*)d_in[6];
    const float* ln_g  = (const float*)d_in[7];
    const float* ln_b  = (const float*)d_in[8];
    const float* fcW   = (const float*)d_in[9];
    const float* fcb   = (const float*)d_in[10];
    float* out = (float*)d_out;

    // Resolve __device__ scratch (no allocation; symbol lookup is capture-safe)
    float *h1, *h2, *Wf, *bf;
    cudaGetSymbolAddress((void**)&h1, g_h1);
    cudaGetSymbolAddress((void**)&h2, g_h2);
    cudaGetSymbolAddress((void**)&Wf, g_Wf);
    cudaGetSymbolAddress((void**)&bf, g_bf);

    dim3 blk(NTHREADS);

    // GEMM1: h1 = tanh(x @ W0^T + b_ih0 + b_hh0)   [4096,2048], K=4096
    {
        dim3 grid(HID / BN, BATCH / BM);
        gemm_nt_kernel<true, false><<<grid, blk>>>(x, W0, b_ih0, b_hh0, h1,
                                                   BATCH, HID, DIN);
    }
    // GEMM2: h2 = tanh(h1 @ W1^T + b_ih1 + b_hh1)  [4096,2048], K=2048
    {
        dim3 grid(HID / BN, BATCH / BM);
        gemm_nt_kernel<true, false><<<grid, blk>>>(h1, W1, b_ih1, b_hh1, h2,
                                                   BATCH, HID, HID);
    }
    // Fold fc weight/bias (independent of the GEMMs above; tiny)
    prep_w_kernel<<<(DOUT * HID + 255) / 256, 256>>>(fcW, ln_g, Wf);
    prep_b_kernel<<<DOUT, 256>>>(fcW, ln_b, fcb, bf);

    // LayerNorm rows -> z (reuse h1 buffer)
    rowln_kernel<<<BATCH, 256>>>(h2, h1);

    // GEMM3: out = z @ Wf^T + bf  [4096,1000], K=2048 (N guarded)
    {
        dim3 grid((DOUT + BN - 1) / BN, BATCH / BM);
        gemm_nt_kernel<false, true><<<grid, blk>>>(h1, Wf, bf, nullptr, out,
                                                   BATCH, DOUT, HID);
    }
}

// round 3
// speedup vs baseline: 2.1026x; 2.1026x over previous
#include <cuda_runtime.h>
#include <cuda_fp16.h>
#include <math.h>
#include <stdint.h>

// ---------------- problem dims ----------------
#define BATCH 4096
#define DIN   4096
#define HID   2048
#define DOUT  1000
#define DOUTP 1024
#define LN_EPS 1e-5f
#define K1EXT (3*DIN)       // 12288
#define K2EXT (3*HID)       // 6144

// ---------------- scratch ----------------
__device__ __half g_xext [(size_t)BATCH*K1EXT];
__device__ __half g_w0ext[(size_t)HID  *K1EXT];
__device__ __half g_w1ext[(size_t)HID  *K2EXT];
__device__ __half g_wfext[(size_t)DOUTP*K2EXT];
__device__ __half g_h1ext[(size_t)BATCH*K2EXT];
__device__ __half g_zext [(size_t)BATCH*K2EXT];
__device__ float g_h2[(size_t)BATCH*HID];
__device__ float g_bf[DOUTP];

// ---------------- PTX helpers (sm_80-level only; no 'a' features) ----------------
__device__ __forceinline__ uint32_t smem_u32(const void* p) {
    uint32_t a;
    asm("{ .reg .u64 t; cvta.to.shared.u64 t, %1; cvt.u32.u64 %0, t; }"
        : "=r"(a) : "l"(p));
    return a;
}
__device__ __forceinline__ void cp16(uint32_t s, const void* g) {
    asm volatile("cp.async.cg.shared.global [%0], [%1], 16;" :: "r"(s), "l"(g));
}
#define CP_COMMIT() asm volatile("cp.async.commit_group;" ::: "memory")
#define CP_WAIT2()  asm volatile("cp.async.wait_group 2;"  ::: "memory")

#define LDSM4(r0,r1,r2,r3, addr) \
    asm volatile("ldmatrix.sync.aligned.m8n8.x4.shared.b16 {%0,%1,%2,%3}, [%4];" \
        : "=r"(r0),"=r"(r1),"=r"(r2),"=r"(r3) : "r"(addr))

__device__ __forceinline__ void mma16816(float* c, const uint32_t* a, const uint32_t* b) {
    asm volatile("mma.sync.aligned.m16n8k16.row.col.f32.f16.f16.f32 "
        "{%0,%1,%2,%3}, {%4,%5,%6,%7}, {%8,%9}, {%0,%1,%2,%3};"
        : "+f"(c[0]),"+f"(c[1]),"+f"(c[2]),"+f"(c[3])
        : "r"(a[0]),"r"(a[1]),"r"(a[2]),"r"(a[3]), "r"(b[0]),"r"(b[1]));
}

// ---------------- tiling ----------------
#define BK 32
#define STAGES 4
#define ROWB 80                      // padded smem row: 32 halfs + 8 pad = 80B
#define A_BYTES (128*ROWB)           // 10240
#define STAGE_BYTES (2*A_BYTES)      // 20480
#define GEMM_DSMEM (STAGES*STAGE_BYTES)   // 81920
#define EPI_LD 66                    // fp32 stride of epilogue stage

// MODE 0: tanh(acc+b1+b2) -> fp16x3 ext (outE, row stride 3*Nf)
// MODE 1: tanh(acc+b1+b2) -> fp32 (outF, row stride Nf)
// MODE 2: acc+b1 -> fp32 (outF, row stride DOUT, store-guard n<DOUT)
template<int MODE>
__global__ __launch_bounds__(256, 2)
void gemm_mma(const __half* __restrict__ A, const __half* __restrict__ B,
              const float* __restrict__ b1, const float* __restrict__ b2,
              __half* __restrict__ outE, float* __restrict__ outF,
              int Kext, int Nf)
{
    extern __shared__ char smem[];
    const uint32_t sb = smem_u32(smem);
    const int tid = threadIdx.x, lane = tid & 31, wid = tid >> 5;
    const int warp_m = wid & 3, warp_n = wid >> 2;
    const int n0 = blockIdx.x * 128, m0 = blockIdx.y * 128;

    float c[2][8][4];
    #pragma unroll
    for (int i = 0; i < 2; i++)
        #pragma unroll
        for (int j = 0; j < 8; j++)
            #pragma unroll
            for (int l = 0; l < 4; l++) c[i][j][l] = 0.f;

    // cp.async coords: 512 16B-chunks per operand tile, 2 per thread
    const int ldr = tid >> 2;          // row (0..63), +64 on second chunk
    const int ldc = tid & 3;           // 16B chunk within row

    const __half* gA = A + (size_t)(m0 + ldr) * Kext + ldc * 8;
    const __half* gB = B + (size_t)(n0 + ldr) * Kext + ldc * 8;
    const size_t rowJmpA = (size_t)64 * Kext;

    // ldmatrix per-lane byte offsets within a stage
    const uint32_t aoff = (uint32_t)(warp_m * 32 + (lane & 15)) * ROWB + (lane >> 4) * 16;
    const uint32_t boff = (uint32_t)(warp_n * 64 + (lane & 7) + (lane >> 4) * 8) * ROWB
                        + ((lane >> 3) & 1) * 16;

    const int NC = Kext / BK;

    // prologue: stages 0..2
    #pragma unroll
    for (int s = 0; s < STAGES - 1; s++) {
        uint32_t sA = sb + s * STAGE_BYTES;
        uint32_t so = sA + (uint32_t)ldr * ROWB + ldc * 16;
        cp16(so,                   gA + (size_t)s * BK);
        cp16(so + 64u * ROWB,      gA + (size_t)s * BK + rowJmpA);
        cp16(so + A_BYTES,         gB + (size_t)s * BK);
        cp16(so + A_BYTES + 64u * ROWB, gB + (size_t)s * BK + rowJmpA);
        CP_COMMIT();
    }

    for (int kc = 0; kc < NC; kc++) {
        CP_WAIT2();
        __syncthreads();

        // prefetch stage kc+3
        if (kc + STAGES - 1 < NC) {
            int s = (kc + STAGES - 1) & (STAGES - 1);
            size_t kt = (size_t)(kc + STAGES - 1) * BK;
            uint32_t sA = sb + s * STAGE_BYTES;
            uint32_t so = sA + (uint32_t)ldr * ROWB + ldc * 16;
            cp16(so,                   gA + kt);
            cp16(so + 64u * ROWB,      gA + kt + rowJmpA);
            cp16(so + A_BYTES,         gB + kt);
            cp16(so + A_BYTES + 64u * ROWB, gB + kt + rowJmpA);
        }
        CP_COMMIT();

        const uint32_t sA = sb + (kc & (STAGES - 1)) * STAGE_BYTES;
        const uint32_t sB = sA + A_BYTES;
        #pragma unroll
        for (int ks = 0; ks < 2; ks++) {
            uint32_t a[2][4], b[8][2];
            #pragma unroll
            for (int mi = 0; mi < 2; mi++)
                LDSM4(a[mi][0], a[mi][1], a[mi][2], a[mi][3],
                      sA + aoff + mi * (16 * ROWB) + ks * 32);
            #pragma unroll
            for (int nt = 0; nt < 4; nt++)
                LDSM4(b[2*nt][0], b[2*nt][1], b[2*nt+1][0], b[2*nt+1][1],
                      sB + boff + nt * (16 * ROWB) + ks * 32);
            #pragma unroll
            for (int mi = 0; mi < 2; mi++)
                #pragma unroll
                for (int nj = 0; nj < 8; nj++)
                    mma16816(c[mi][nj], a[mi], b[nj]);
        }
    }

    // -------- epilogue: stage through smem for coalesced global traffic --------
    float* epi = (float*)smem;     // 128 x 66 fp32 = 33792 B (fits in stage smem)
    #pragma unroll 1
    for (int h = 0; h < 2; h++) {
        __syncthreads();
        if (warp_n == h) {
            #pragma unroll
            for (int mi = 0; mi < 2; mi++)
                #pragma unroll
                for (int nj = 0; nj < 8; nj++) {
                    int row = warp_m * 32 + mi * 16 + (lane >> 2);
                    int col = nj * 8 + (lane & 3) * 2;
                    epi[row * EPI_LD + col]           = c[mi][nj][0];
                    epi[row * EPI_LD + col + 1]       = c[mi][nj][1];
                    epi[(row + 8) * EPI_LD + col]     = c[mi][nj][2];
                    epi[(row + 8) * EPI_LD + col + 1] = c[mi][nj][3];
                }
        }
        __syncthreads();

        const int col = tid & 63, rb = tid >> 6;
        const int n = n0 + h * 64 + col;
        float bb = b1[n];
        if (MODE != 2) bb += b2[n];
        #pragma unroll 4
        for (int i = 0; i < 32; i++) {
            int row = i * 4 + rb;
            float v = epi[row * EPI_LD + col] + bb;
            if (MODE != 2) v = tanhf(v);
            int m = m0 + row;
            if (MODE == 0) {
                __half hi = __float2half(v);
                __half lo = __float2half(v - __half2float(hi));
                size_t base = (size_t)m * (3 * Nf) + n;
                outE[base] = hi; outE[base + Nf] = lo; outE[base + 2 * Nf] = hi;
            } else if (MODE == 1) {
                outF[(size_t)m * Nf + n] = v;
            } else {
                if (n < DOUT) outF[(size_t)m * DOUT + n] = v;
            }
        }
    }
}

// ---------------- splits / prep ----------------
__device__ __forceinline__ void split2(float v, __half& hi, __half& lo) {
    hi = __float2half(v);
    lo = __float2half(v - __half2float(hi));
}
// A-pattern: [hi | lo | hi]
__global__ __launch_bounds__(256)
void split_a(const float* __restrict__ src, __half* __restrict__ dst, int R, int C) {
    int idx = blockIdx.x * 256 + threadIdx.x;
    if (idx >= R * C) return;
    int r = idx / C, cc = idx - r * C;
    __half hi, lo; split2(src[idx], hi, lo);
    size_t b = (size_t)r * 3 * C + cc;
    dst[b] = hi; dst[b + C] = lo; dst[b + 2 * C] = hi;
}
// B-pattern: [hi | hi | lo]
__global__ __launch_bounds__(256)
void split_b(const float* __restrict__ src, __half* __restrict__ dst, int R, int C) {
    int idx = blockIdx.x * 256 + threadIdx.x;
    if (idx >= R * C) return;
    int r = idx / C, cc = idx - r * C;
    __half hi, lo; split2(src[idx], hi, lo);
    size_t b = (size_t)r * 3 * C + cc;
    dst[b] = hi; dst[b + C] = hi; dst[b + 2 * C] = lo;
}
// Wf fold + B-pattern split (rows padded to DOUTP with zeros)
__global__ __launch_bounds__(256)
void prep_wf(const float* __restrict__ fcW, const float* __restrict__ ln_g,
             __half* __restrict__ dst) {
    int idx = blockIdx.x * 256 + threadIdx.x;
    if (idx >= DOUTP * HID) return;
    int o = idx / HID, j = idx - o * HID;
    float v = 0.f;
    if (o < DOUT) {
        const float* wr = fcW + (size_t)o * (2 * HID);
        v = ln_g[j] * wr[j] + ln_g[HID + j] * wr[HID + j];
    }
    __half hi, lo; split2(v, hi, lo);
    size_t b = (size_t)o * K2EXT + j;
    dst[b] = hi; dst[b + HID] = hi; dst[b + 2 * HID] = lo;
}
__global__ __launch_bounds__(256)
void prep_bf(const float* __restrict__ fcW, const float* __restrict__ ln_b,
             const float* __restrict__ fcb, float* __restrict__ bf) {
    int o = blockIdx.x;
    if (o >= DOUT) { if (threadIdx.x == 0) bf[o] = 0.f; return; }
    const float* wr = fcW + (size_t)o * (2 * HID);
    float s = 0.f;
    for (int j = threadIdx.x; j < 2 * HID; j += 256) s = fmaf(ln_b[j], wr[j], s);
    #pragma unroll
    for (int ofs = 16; ofs > 0; ofs >>= 1) s += __shfl_xor_sync(0xffffffffu, s, ofs);
    __shared__ float ss[8];
    if ((threadIdx.x & 31) == 0) ss[threadIdx.x >> 5] = s;
    __syncthreads();
    if (threadIdx.x == 0) {
        float a = 0.f;
        #pragma unroll
        for (int i = 0; i < 8; i++) a += ss[i];
        bf[o] = fcb[o] + a;
    }
}

// ---------------- row LayerNorm -> A-pattern fp16x3 ----------------
__global__ __launch_bounds__(256)
void rowln(const float* __restrict__ h2, __half* __restrict__ zext) {
    const int row = blockIdx.x;
    const float* src = h2 + (size_t)row * HID;
    float vals[8];
    float s = 0.f, s2 = 0.f;
    #pragma unroll
    for (int i = 0; i < 8; i++) {
        float v = src[threadIdx.x + i * 256];
        vals[i] = v; s += v; s2 = fmaf(v, v, s2);
    }
    #pragma unroll
    for (int o = 16; o > 0; o >>= 1) {
        s  += __shfl_xor_sync(0xffffffffu, s,  o);
        s2 += __shfl_xor_sync(0xffffffffu, s2, o);
    }
    __shared__ float ss[8], ss2[8];
    int w = threadIdx.x >> 5;
    if ((threadIdx.x & 31) == 0) { ss[w] = s; ss2[w] = s2; }
    __syncthreads();
    if (threadIdx.x < 32) {
        float a  = (threadIdx.x < 8) ? ss[threadIdx.x]  : 0.f;
        float a2 = (threadIdx.x < 8) ? ss2[threadIdx.x] : 0.f;
        #pragma unroll
        for (int o = 4; o > 0; o >>= 1) {
            a  += __shfl_xor_sync(0xffffffffu, a,  o);
            a2 += __shfl_xor_sync(0xffffffffu, a2, o);
        }
        if (threadIdx.x == 0) { ss[0] = a; ss2[0] = a2; }
    }
    __syncthreads();
    const float inv = 1.f / (float)HID;
    float mu = ss[0] * inv;
    float rs = rsqrtf(ss2[0] * inv - mu * mu + LN_EPS);
    #pragma unroll
    for (int i = 0; i < 8; i++) {
        float v = (vals[i] - mu) * rs;
        __half hi, lo; split2(v, hi, lo);
        size_t b = (size_t)row * K2EXT + threadIdx.x + i * 256;
        zext[b] = hi; zext[b + HID] = lo; zext[b + 2 * HID] = hi;
    }
}

// ---------------- launcher ----------------
extern "C" void kernel_launch(void* const* d_in, const int* in_sizes, int n_in,
                              void* d_out, int out_size)
{
    const float* x     = (const float*)d_in[0];
    const float* W0    = (const float*)d_in[1];
    const float* b_ih0 = (const float*)d_in[2];
    const float* b_hh0 = (const float*)d_in[3];
    const float* W1    = (const float*)d_in[4];
    const float* b_ih1 = (const float*)d_in[5];
    const float* b_hh1 = (const float*)d_in[6];
    const float* ln_g  = (const float*)d_in[7];
    const float* ln_b  = (const float*)d_in[8];
    const float* fcW   = (const float*)d_in[9];
    const float* fcb   = (const float*)d_in[10];
    float* out = (float*)d_out;

    __half *xext, *w0e, *w1e, *wfe, *h1e, *ze;
    float *h2, *bf;
    cudaGetSymbolAddress((void**)&xext, g_xext);
    cudaGetSymbolAddress((void**)&w0e,  g_w0ext);
    cudaGetSymbolAddress((void**)&w1e,  g_w1ext);
    cudaGetSymbolAddress((void**)&wfe,  g_wfext);
    cudaGetSymbolAddress((void**)&h1e,  g_h1ext);
    cudaGetSymbolAddress((void**)&ze,   g_zext);
    cudaGetSymbolAddress((void**)&h2,   g_h2);
    cudaGetSymbolAddress((void**)&bf,   g_bf);

    cudaFuncSetAttribute(gemm_mma<0>, cudaFuncAttributeMaxDynamicSharedMemorySize, GEMM_DSMEM);
    cudaFuncSetAttribute(gemm_mma<1>, cudaFuncAttributeMaxDynamicSharedMemorySize, GEMM_DSMEM);
    cudaFuncSetAttribute(gemm_mma<2>, cudaFuncAttributeMaxDynamicSharedMemorySize, GEMM_DSMEM);

    split_a<<<(BATCH * DIN + 255) / 256, 256>>>(x,  xext, BATCH, DIN);
    split_b<<<(HID * DIN + 255) / 256, 256>>>(W0, w0e, HID, DIN);
    split_b<<<(HID * HID + 255) / 256, 256>>>(W1, w1e, HID, HID);
    prep_wf<<<(DOUTP * HID + 255) / 256, 256>>>(fcW, ln_g, wfe);
    prep_bf<<<DOUTP, 256>>>(fcW, ln_b, fcb, bf);

    // GEMM1: h1ext = split(tanh(x @ W0^T + b_ih0 + b_hh0))
    gemm_mma<0><<<dim3(HID / 128, BATCH / 128), 256, GEMM_DSMEM>>>(
        xext, w0e, b_ih0, b_hh0, h1e, nullptr, K1EXT, HID);
    // GEMM2: h2 = tanh(h1 @ W1^T + b_ih1 + b_hh1)
    gemm_mma<1><<<dim3(HID / 128, BATCH / 128), 256, GEMM_DSMEM>>>(
        h1e, w1e, b_ih1, b_hh1, nullptr, h2, K2EXT, HID);
    // LayerNorm rows -> zext
    rowln<<<BATCH, 256>>>(h2, ze);
    // GEMM3: out = z @ Wf^T + bf
    gemm_mma<2><<<dim3(DOUTP / 128, BATCH / 128), 256, GEMM_DSMEM>>>(
        ze, wfe, bf, nullptr, nullptr, out, K2EXT, DOUT);
}